// round 5
// baseline (speedup 1.0000x reference)
#include <cuda_runtime.h>
#include <math.h>

#define B_   8
#define N_   2000
#define T_   8
#define F_   128
#define DEG_ 8
#define H_   4
#define D1_  64
#define D2_  64
#define G_   64
#define PW_  16
#define BT_  (B_*T_)     // 64
#define SEQ_ (N_*T_)     // 16000
#define HD_  (H_*D1_)    // 256

// -------- scratch (static device arrays are the sanctioned scratch path) --------
__device__ float g_z1  [(size_t)BT_*N_*HD_];            // 131 MB
__device__ float g_h1  [(size_t)BT_*N_*HD_];            // 131 MB
__device__ float g_z2  [(size_t)BT_*N_*D2_];            // 33 MB
__device__ float g_seqT[(size_t)SEQ_*B_*D2_];           // 33 MB  (xs layout: [s][b][d])
__device__ float g_gi  [(size_t)SEQ_*B_*3*G_ + 8192];   // 98 MB + prefetch pad
__device__ float g_ssrc1[BT_*H_*N_];
__device__ float g_sdst1[BT_*H_*N_];
__device__ float g_ssrc2[BT_*N_];
__device__ float g_sdst2[BT_*N_];
__device__ float g_hloc[(size_t)N_*B_*G_];              // [n][b][g]
__device__ float g_W1cat[F_*HD_];                       // [f][h*64+d]
__device__ float g_WihT [D2_*3*G_];                     // [d][j]

// ---------------------------------------------------------------------------
// f32x2 packed helpers (sm_103a: FFMA2 only reachable via PTX)
__device__ __forceinline__ unsigned long long ffma2_(unsigned long long a,
                                                     unsigned long long b,
                                                     unsigned long long c)
{
    unsigned long long d;
    asm("fma.rn.f32x2 %0, %1, %2, %3;" : "=l"(d) : "l"(a), "l"(b), "l"(c));
    return d;
}
__device__ __forceinline__ unsigned long long fadd2_(unsigned long long a,
                                                     unsigned long long b)
{
    unsigned long long d;
    asm("add.rn.f32x2 %0, %1, %2;" : "=l"(d) : "l"(a), "l"(b));
    return d;
}
__device__ __forceinline__ unsigned long long pack2_(float x, float y)
{
    unsigned long long p;
    asm("mov.b64 %0, {%1, %2};" : "=l"(p) : "f"(x), "f"(y));
    return p;
}
__device__ __forceinline__ float unpack_sum_(unsigned long long s)
{
    float lo, hi;
    asm("mov.b64 {%0, %1}, %2;" : "=f"(lo), "=f"(hi) : "l"(s));
    return lo + hi;
}
__device__ __forceinline__ void unpack2_(unsigned long long s, float& lo, float& hi)
{
    asm("mov.b64 {%0, %1}, %2;" : "=f"(lo), "=f"(hi) : "l"(s));
}
// sigmoid: EX2 + RCP (saturates cleanly at +/-inf, no NaN)
__device__ __forceinline__ float sigmoid_fast(float x)
{
    float e = __expf(-x);
    float inv;
    asm("rcp.approx.f32 %0, %1;" : "=f"(inv) : "f"(1.0f + e));
    return inv;
}

// ---------------------------------------------------------------------------
// Pack W1 -> [F, H*D1] and Wih -> [D2, 3G]
__global__ void pack_kernel(const float* __restrict__ W1, const float* __restrict__ Wih)
{
    int i = blockIdx.x * 256 + threadIdx.x;
    if (i < F_*HD_) {
        int f = i / HD_, c = i % HD_;
        int h = c >> 6, d = c & 63;
        g_W1cat[i] = W1[((size_t)h*F_ + f)*D1_ + d];
    }
    if (i < D2_*3*G_) {
        int d = i / (3*G_), j = i % (3*G_);
        g_WihT[i] = Wih[(size_t)j*D2_ + d];
    }
}

// ---------------------------------------------------------------------------
// Tiled SGEMM (f32x2 accumulate): C[z] = A[z] (MxK) * Bm (KxN) + bias.
// BM=128 BN=64 BK=16; microtile 8x4 held as 4 row-pairs x 4 cols in f32x2.
__global__ void __launch_bounds__(256)
gemm_bias(const float* __restrict__ A, const float* __restrict__ Bm,
          const float* __restrict__ bias, float* __restrict__ C,
          int M, int N, int K, int lda, int ldc,
          long aOuter, long aInner, int innerCnt, long cStride)
{
    __shared__ float As[16][128];
    __shared__ float Bs[16][64];

    int z = blockIdx.z;
    const float* Ab = A + (long)(z / innerCnt) * aOuter + (long)(z % innerCnt) * aInner;
    float* Cb = C + (long)z * cStride;
    int m0 = blockIdx.x * 128;
    int n0 = blockIdx.y * 64;
    int tid = threadIdx.x;
    int tx = tid & 15;          // col group  (4 cols)
    int ty = tid >> 4;          // row group  (8 rows = 4 pairs)

    unsigned long long accp[4][4];
#pragma unroll
    for (int q = 0; q < 4; q++)
#pragma unroll
        for (int j = 0; j < 4; j++) accp[q][j] = 0ull;

    for (int k0 = 0; k0 < K; k0 += 16) {
        // A tile: 128x16, 2 float4 per thread, store transposed
#pragma unroll
        for (int q = 0; q < 2; q++) {
            int l4  = tid * 2 + q;
            int row = l4 >> 2;
            int c4  = (l4 & 3) << 2;
            int gm  = m0 + row; if (gm > M - 1) gm = M - 1;
            float4 v = *reinterpret_cast<const float4*>(Ab + (long)gm * lda + k0 + c4);
            As[c4 + 0][row] = v.x; As[c4 + 1][row] = v.y;
            As[c4 + 2][row] = v.z; As[c4 + 3][row] = v.w;
        }
        { // B tile: 16x64, 1 float4 per thread
            int row = tid >> 4;
            int c4  = (tid & 15) << 2;
            float4 v = *reinterpret_cast<const float4*>(Bm + (long)(k0 + row) * N + n0 + c4);
            *reinterpret_cast<float4*>(&Bs[row][c4]) = v;
        }
        __syncthreads();
#pragma unroll
        for (int kk = 0; kk < 16; kk++) {
            ulonglong2 a01 = *reinterpret_cast<const ulonglong2*>(&As[kk][ty * 8]);
            ulonglong2 a23 = *reinterpret_cast<const ulonglong2*>(&As[kk][ty * 8 + 4]);
            float4 bv = *reinterpret_cast<const float4*>(&Bs[kk][tx * 4]);
            unsigned long long bd0 = pack2_(bv.x, bv.x);
            unsigned long long bd1 = pack2_(bv.y, bv.y);
            unsigned long long bd2 = pack2_(bv.z, bv.z);
            unsigned long long bd3 = pack2_(bv.w, bv.w);
            accp[0][0] = ffma2_(bd0, a01.x, accp[0][0]);
            accp[0][1] = ffma2_(bd1, a01.x, accp[0][1]);
            accp[0][2] = ffma2_(bd2, a01.x, accp[0][2]);
            accp[0][3] = ffma2_(bd3, a01.x, accp[0][3]);
            accp[1][0] = ffma2_(bd0, a01.y, accp[1][0]);
            accp[1][1] = ffma2_(bd1, a01.y, accp[1][1]);
            accp[1][2] = ffma2_(bd2, a01.y, accp[1][2]);
            accp[1][3] = ffma2_(bd3, a01.y, accp[1][3]);
            accp[2][0] = ffma2_(bd0, a23.x, accp[2][0]);
            accp[2][1] = ffma2_(bd1, a23.x, accp[2][1]);
            accp[2][2] = ffma2_(bd2, a23.x, accp[2][2]);
            accp[2][3] = ffma2_(bd3, a23.x, accp[2][3]);
            accp[3][0] = ffma2_(bd0, a23.y, accp[3][0]);
            accp[3][1] = ffma2_(bd1, a23.y, accp[3][1]);
            accp[3][2] = ffma2_(bd2, a23.y, accp[3][2]);
            accp[3][3] = ffma2_(bd3, a23.y, accp[3][3]);
        }
        __syncthreads();
    }

#pragma unroll
    for (int q = 0; q < 4; q++) {
        int gm = m0 + ty * 8 + 2 * q;
#pragma unroll
        for (int j = 0; j < 4; j++) {
            int gn = n0 + tx * 4 + j;
            float lo, hi;
            unpack2_(accp[q][j], lo, hi);
            float bb = bias[gn];
            if (gm < M)     Cb[(long)gm * ldc + gn]       = lo + bb;
            if (gm + 1 < M) Cb[(long)(gm + 1) * ldc + gn] = hi + bb;
        }
    }
}

// ---------------------------------------------------------------------------
// Attention scores layer 1
__global__ void scores1_kernel(const float* __restrict__ a1)
{
    int gw   = (blockIdx.x * blockDim.x + threadIdx.x) >> 5;
    int lane = threadIdx.x & 31;
    if (gw >= BT_ * N_) return;
    int bt = gw / N_, n = gw % N_;
    const float* zr = g_z1 + ((size_t)bt * N_ + n) * HD_;
#pragma unroll
    for (int h = 0; h < H_; h++) {
        float s = 0.f, d = 0.f;
#pragma unroll
        for (int q = 0; q < 2; q++) {
            int dd = lane + 32 * q;
            float zv = zr[h * 64 + dd];
            s = fmaf(zv, a1[h * 128 + dd], s);
            d = fmaf(zv, a1[h * 128 + 64 + dd], d);
        }
#pragma unroll
        for (int o = 16; o >= 1; o >>= 1) {
            s += __shfl_xor_sync(0xffffffffu, s, o);
            d += __shfl_xor_sync(0xffffffffu, d, o);
        }
        if (lane == 0) {
            g_ssrc1[(bt * H_ + h) * N_ + n] = s;
            g_sdst1[(bt * H_ + h) * N_ + n] = d;
        }
    }
}

__global__ void scores2_kernel(const float* __restrict__ a2)
{
    int gw   = (blockIdx.x * blockDim.x + threadIdx.x) >> 5;
    int lane = threadIdx.x & 31;
    if (gw >= BT_ * N_) return;
    int bt = gw / N_, n = gw % N_;
    const float* zr = g_z2 + ((size_t)bt * N_ + n) * D2_;
    float s = 0.f, d = 0.f;
#pragma unroll
    for (int q = 0; q < 2; q++) {
        int dd = lane + 32 * q;
        float zv = zr[dd];
        s = fmaf(zv, a2[dd],      s);
        d = fmaf(zv, a2[64 + dd], d);
    }
#pragma unroll
    for (int o = 16; o >= 1; o >>= 1) {
        s += __shfl_xor_sync(0xffffffffu, s, o);
        d += __shfl_xor_sync(0xffffffffu, d, o);
    }
    if (lane == 0) { g_ssrc2[bt * N_ + n] = s; g_sdst2[bt * N_ + n] = d; }
}

// ---------------------------------------------------------------------------
// GAT attention layer 1: warp per (bt,n), 4 heads, softmax over 8 neighbors, ELU
__global__ void attn1_kernel(const int* __restrict__ src, const float* __restrict__ a1b)
{
    int gw   = (blockIdx.x * blockDim.x + threadIdx.x) >> 5;
    int lane = threadIdx.x & 31;
    if (gw >= BT_ * N_) return;
    int bt = gw / N_, n = gw % N_;

    int sk = 0;
    if (lane < 8) sk = src[n * DEG_ + lane];

#pragma unroll
    for (int h = 0; h < H_; h++) {
        float sd = g_sdst1[(bt * H_ + h) * N_ + n];
        float e = -1e30f;
        if (lane < 8) {
            float v = g_ssrc1[(bt * H_ + h) * N_ + sk] + sd + a1b[h];
            e = (v > 0.f) ? v : 0.01f * v;
        }
        float m = e;
#pragma unroll
        for (int o = 4; o >= 1; o >>= 1) m = fmaxf(m, __shfl_xor_sync(0xffffffffu, m, o, 8));
        float p = __expf(e - m);
        float sum = p;
#pragma unroll
        for (int o = 4; o >= 1; o >>= 1) sum += __shfl_xor_sync(0xffffffffu, sum, o, 8);
        float alpha = p / sum;

        float acc0 = 0.f, acc1 = 0.f;
#pragma unroll
        for (int k = 0; k < 8; k++) {
            float al = __shfl_sync(0xffffffffu, alpha, k);
            int   s2 = __shfl_sync(0xffffffffu, sk, k);
            const float* zrow = g_z1 + ((size_t)bt * N_ + s2) * HD_ + h * 64;
            acc0 = fmaf(al, zrow[lane],      acc0);
            acc1 = fmaf(al, zrow[lane + 32], acc1);
        }
        size_t o = ((size_t)bt * N_ + n) * HD_ + h * 64 + lane;
        g_h1[o]      = acc0 > 0.f ? acc0 : expm1f(acc0);
        g_h1[o + 32] = acc1 > 0.f ? acc1 : expm1f(acc1);
    }
}

// GAT attention layer 2 (single head), writes directly into xs layout [s][b][d]
__global__ void attn2_kernel(const int* __restrict__ src, const float* __restrict__ a2b)
{
    int gw   = (blockIdx.x * blockDim.x + threadIdx.x) >> 5;
    int lane = threadIdx.x & 31;
    if (gw >= BT_ * N_) return;
    int bt = gw / N_, n = gw % N_;
    int b = bt / T_, t = bt % T_;

    int sk = 0;
    if (lane < 8) sk = src[n * DEG_ + lane];

    float sd = g_sdst2[bt * N_ + n];
    float e = -1e30f;
    if (lane < 8) {
        float v = g_ssrc2[bt * N_ + sk] + sd + a2b[0];
        e = (v > 0.f) ? v : 0.01f * v;
    }
    float m = e;
#pragma unroll
    for (int o = 4; o >= 1; o >>= 1) m = fmaxf(m, __shfl_xor_sync(0xffffffffu, m, o, 8));
    float p = __expf(e - m);
    float sum = p;
#pragma unroll
    for (int o = 4; o >= 1; o >>= 1) sum += __shfl_xor_sync(0xffffffffu, sum, o, 8);
    float alpha = p / sum;

    float acc0 = 0.f, acc1 = 0.f;
#pragma unroll
    for (int k = 0; k < 8; k++) {
        float al = __shfl_sync(0xffffffffu, alpha, k);
        int   s2 = __shfl_sync(0xffffffffu, sk, k);
        const float* zrow = g_z2 + ((size_t)bt * N_ + s2) * D2_;
        acc0 = fmaf(al, zrow[lane],      acc0);
        acc1 = fmaf(al, zrow[lane + 32], acc1);
    }
    int srow = (n * T_ + t) * B_ + b;
    size_t o = (size_t)srow * D2_ + lane;
    g_seqT[o]      = acc0 > 0.f ? acc0 : expm1f(acc0);
    g_seqT[o + 32] = acc1 > 0.f ? acc1 : expm1f(acc1);
}

// ---------------------------------------------------------------------------
// GRU scan v3: 8 blocks (one per chain), 256 threads (8 warps).
// Warp w owns units u = w*8+m.  Lane l = g*8+m computes the FULL 64-wide dot
// for gate g of unit u (f32x2).  Gate specialization: one sigma pass for r/z,
// shfl r, one sigma pass for n (tanh = 2*sigma(2y)-1).  h_u carried in a
// register.  ONE __syncthreads per step (double-buffered h).  Prefetch via
// walking pointer into padded g_gi.
template <bool STORE>
__device__ __forceinline__ void gru_step(
    const float* __restrict__ hr, float* __restrict__ hw,
    const unsigned long long* __restrict__ wp, float bj,
    float& qcur, const float*& pf, long STRIDE,
    float& h_u, int m, int u, bool writer, int b, int st)
{
    float qn = __ldg(pf); pf += STRIDE;

    const ulonglong2* h2 = reinterpret_cast<const ulonglong2*>(hr);
    unsigned long long a0 = 0ull, a1 = 0ull, a2 = 0ull, a3 = 0ull;
#pragma unroll
    for (int k = 0; k < 8; k++) {
        ulonglong2 v0 = h2[2 * k];
        ulonglong2 v1 = h2[2 * k + 1];
        a0 = ffma2_(wp[4 * k + 0], v0.x, a0);
        a1 = ffma2_(wp[4 * k + 1], v0.y, a1);
        a2 = ffma2_(wp[4 * k + 2], v1.x, a2);
        a3 = ffma2_(wp[4 * k + 3], v1.y, a3);
    }
    float gh = unpack_sum_(fadd2_(fadd2_(a0, a1), fadd2_(a2, a3)));

    float A  = qcur;            // gi_j (incl. bih)
    float Bv = gh + bj;         // gh_j + bhh_j
    const unsigned msk = 0xffffffffu;

    // phase 1: sigma(A+Bv)  (meaningful on r- and z-lanes)
    float sig1 = sigmoid_fast(A + Bv);
    float r = __shfl_sync(msk, sig1, m);
    // phase 2: n = tanh(A + r*Bv) = 2*sigma(2*(A+r*Bv)) - 1  (n-lanes)
    float y    = fmaf(r, Bv, A);
    float sig2 = sigmoid_fast(2.f * y);
    float nv   = fmaf(2.f, sig2, -1.f);

    float z  = __shfl_sync(msk, sig1, 8 + m);
    float nn = __shfl_sync(msk, nv,  16 + m);
    float hn = fmaf(z, h_u - nn, nn);          // (1-z)*n + z*h

    if (writer) {
        hw[u] = hn;
        if (STORE)
            g_hloc[((size_t)(st >> 3) * B_ + b) * G_ + u] = hn;
    }
    h_u  = hn;
    qcur = qn;
    __syncthreads();
}

__global__ void __launch_bounds__(256, 1)
gru_scan(const float* __restrict__ gi, const float* __restrict__ h0,
         const float* __restrict__ Whh, const float* __restrict__ bhh)
{
    const int b   = blockIdx.x;
    const int tid = threadIdx.x;
    const int w   = tid >> 5;
    const int l   = tid & 31;
    const int m   = l & 7;
    const int g   = (l < 24) ? (l >> 3) : 0;   // idle lanes alias gate 0 (harmless)
    const int u   = w * 8 + m;
    const int j   = g * 64 + u;                // row in [0,192)
    const bool writer = (l < 8);

    unsigned long long wp[32];
    {
        const float* wr = Whh + (size_t)j * 64;
#pragma unroll
        for (int k = 0; k < 32; k++) wp[k] = pack2_(wr[2 * k], wr[2 * k + 1]);
    }
    const float bj = bhh[j];

    __shared__ __align__(16) float h_sh[2][64];
    if (tid < 64) h_sh[0][tid] = h0[b * 64 + tid];
    float h_u = h0[b * 64 + u];                // per-lane carried state
    __syncthreads();

    const long STRIDE = (long)B_ * 192;        // 1536 floats/step
    const float* gp = gi + (long)b * 192 + j;
    const float* pf = gp + 4 * STRIDE;         // walking prefetch pointer

    float q0 = __ldg(gp);
    float q1 = __ldg(gp + STRIDE);
    float q2 = __ldg(gp + 2 * STRIDE);
    float q3 = __ldg(gp + 3 * STRIDE);

    for (int s = 0; s < SEQ_; s += 4) {
        gru_step<false>(h_sh[0], h_sh[1], wp, bj, q0, pf, STRIDE, h_u, m, u, writer, b, s);
        gru_step<false>(h_sh[1], h_sh[0], wp, bj, q1, pf, STRIDE, h_u, m, u, writer, b, s + 1);
        gru_step<false>(h_sh[0], h_sh[1], wp, bj, q2, pf, STRIDE, h_u, m, u, writer, b, s + 2);
        if ((s & 7) == 4)
            gru_step<true >(h_sh[1], h_sh[0], wp, bj, q3, pf, STRIDE, h_u, m, u, writer, b, s + 3);
        else
            gru_step<false>(h_sh[1], h_sh[0], wp, bj, q3, pf, STRIDE, h_u, m, u, writer, b, s + 3);
    }
}

// ---------------------------------------------------------------------------
// Output projection: out[b][n][p] = h_loc[n][b][:] . Wp[:,p] + bp[p]
__global__ void proj_kernel(const float* __restrict__ Wp, const float* __restrict__ bp,
                            float* __restrict__ out)
{
    int gw   = (blockIdx.x * blockDim.x + threadIdx.x) >> 5;
    int lane = threadIdx.x & 31;
    if (gw >= B_ * N_) return;
    int b = gw / N_, n = gw % N_;
    if (lane < PW_) {
        const float* hl = g_hloc + ((size_t)n * B_ + b) * G_;
        float acc = bp[lane];
#pragma unroll
        for (int g = 0; g < G_; g++) acc = fmaf(hl[g], Wp[g * PW_ + lane], acc);
        out[((size_t)b * N_ + n) * PW_ + lane] = acc;
    }
}

// ---------------------------------------------------------------------------
extern "C" void kernel_launch(void* const* d_in, const int* in_sizes, int n_in,
                              void* d_out, int out_size)
{
    const float* dynamic = (const float*)d_in[0];
    const float* h0      = (const float*)d_in[1];
    const int*   src     = (const int*)  d_in[2];
    const float* W1      = (const float*)d_in[3];
    const float* b1      = (const float*)d_in[4];
    const float* a1      = (const float*)d_in[5];
    const float* a1b     = (const float*)d_in[6];
    const float* W2      = (const float*)d_in[7];
    const float* b2      = (const float*)d_in[8];
    const float* a2      = (const float*)d_in[9];
    const float* a2b     = (const float*)d_in[10];
    const float* Wih     = (const float*)d_in[11];
    const float* Whh     = (const float*)d_in[12];
    const float* bih     = (const float*)d_in[13];
    const float* bhh     = (const float*)d_in[14];
    const float* Wp      = (const float*)d_in[15];
    const float* bp      = (const float*)d_in[16];
    float* out = (float*)d_out;

    float *z1p, *h1p, *z2p, *seqTp, *gip, *W1catp, *WihTp;
    cudaGetSymbolAddress((void**)&z1p,    g_z1);
    cudaGetSymbolAddress((void**)&h1p,    g_h1);
    cudaGetSymbolAddress((void**)&z2p,    g_z2);
    cudaGetSymbolAddress((void**)&seqTp,  g_seqT);
    cudaGetSymbolAddress((void**)&gip,    g_gi);
    cudaGetSymbolAddress((void**)&W1catp, g_W1cat);
    cudaGetSymbolAddress((void**)&WihTp,  g_WihT);

    // 0) pack weights
    pack_kernel<<<128, 256>>>(W1, Wih);

    // 1) z1 = x @ W1cat + b1   (per (b,t): 2000x128 @ 128x256)
    gemm_bias<<<dim3(16, 4, BT_), 256>>>(dynamic, W1catp, b1, z1p,
                                         N_, HD_, F_, T_ * F_, HD_,
                                         (long)N_ * T_ * F_, (long)F_, T_,
                                         (long)N_ * HD_);
    // 2) attention scores + aggregation layer 1 -> h1 (ELU)
    scores1_kernel<<<16000, 256>>>(a1);
    attn1_kernel<<<16000, 256>>>(src, a1b);

    // 3) z2 = h1 @ W2 + b2   (per (b,t): 2000x256 @ 256x64)
    gemm_bias<<<dim3(16, 1, BT_), 256>>>(h1p, W2, b2, z2p,
                                         N_, D2_, HD_, HD_, D2_,
                                         (long)N_ * HD_, 0L, 1,
                                         (long)N_ * D2_);
    // 4) attention layer 2 -> seqT (xs layout), ELU
    scores2_kernel<<<16000, 256>>>(a2);
    attn2_kernel<<<16000, 256>>>(src, a2b);

    // 5) gi = seqT @ WihT + bih   (128000x64 @ 64x192)
    gemm_bias<<<dim3(1000, 3, 1), 256>>>(seqTp, WihTp, bih, gip,
                                         SEQ_ * B_, 3 * G_, D2_, D2_, 3 * G_,
                                         0L, 0L, 1, 0L);

    // 6) sequential GRU scan (8 independent chains) — v3
    gru_scan<<<B_, 256>>>(gip, h0, Whh, bhh);

    // 7) projection
    proj_kernel<<<2000, 256>>>(Wp, bp, out);
}